// round 17
// baseline (speedup 1.0000x reference)
#include <cuda_runtime.h>
#include <cuda_fp16.h>
#include <cstdint>
#include <math.h>

#define LL 24
#define NN 8192
#define DIN 256
#define DOUT 128
#define NWX 512     // 4*DOUT
#define NP  1280    // 2 halves * 5 gates * 128

// ---------------- device globals ----------------
__device__ __half g_WxH[(size_t)LL * NN * NWX];          // fp16, [lvl*NN+n][c], c=d*4+gate
__device__ float g_P[(size_t)NN * NP];
__device__ float g_Pinit[NP];
__device__ float g_Upair[(size_t)NP * 128];              // fp32 (for Pinit)
__device__ float g_biasPerm[NWX];
__device__ __half g_Bwh[(size_t)NWX * DIN];              // permuted Ww, fp16
__device__ __half g_Uph[(size_t)NP * 128];               // Upair, fp16

// ---------------- static stream/event resources (host-side only) ----------
struct OverlapRes {
    cudaStream_t s1;
    cudaEvent_t evStart;
    cudaEvent_t ev[LL];
    OverlapRes() {
        cudaStreamCreateWithFlags(&s1, cudaStreamNonBlocking);
        cudaEventCreateWithFlags(&evStart, cudaEventDisableTiming);
        for (int i = 0; i < LL; i++)
            cudaEventCreateWithFlags(&ev[i], cudaEventDisableTiming);
    }
};
static OverlapRes g_res;

__device__ __forceinline__ float sigmoidf_(float x) {
    return 1.0f / (1.0f + __expf(-x));
}

__device__ __forceinline__ uint32_t smem_to_u32(const void* p) {
    uint32_t a;
    asm("{ .reg .u64 t; cvta.to.shared.u64 t, %1; cvt.u32.u64 %0, t; }" : "=r"(a) : "l"(p));
    return a;
}

#define CP_COMMIT() asm volatile("cp.async.commit_group;" ::: "memory")
__device__ __forceinline__ void cpa16(uint32_t d, const void* s) {
    asm volatile("cp.async.cg.shared.global [%0], [%1], 16;" :: "r"(d), "l"(s));
}
__device__ __forceinline__ void ldm_x4(uint32_t a, uint32_t& r0, uint32_t& r1,
                                       uint32_t& r2, uint32_t& r3) {
    asm volatile("ldmatrix.sync.aligned.m8n8.x4.shared.b16 {%0,%1,%2,%3}, [%4];"
                 : "=r"(r0), "=r"(r1), "=r"(r2), "=r"(r3) : "r"(a));
}
__device__ __forceinline__ void mma16816(float* c, const uint32_t* a, const uint32_t* b) {
    asm volatile(
        "mma.sync.aligned.m16n8k16.row.col.f32.f16.f16.f32 "
        "{%0,%1,%2,%3}, {%4,%5,%6,%7}, {%8,%9}, {%0,%1,%2,%3};"
        : "+f"(c[0]), "+f"(c[1]), "+f"(c[2]), "+f"(c[3])
        : "r"(a[0]), "r"(a[1]), "r"(a[2]), "r"(a[3]), "r"(b[0]), "r"(b[1]));
}

// ---------------- prep kernels ----------------
__global__ void build_bw(const float* __restrict__ Ww, const float* __restrict__ Wb) {
    int t = blockIdx.x * blockDim.x + threadIdx.x;
    if (t < NWX) g_biasPerm[t] = Wb[((t & 3) << 7) + (t >> 2)];
    if (t >= NWX * DIN) return;
    int c = t >> 8, k = t & 255;
    int orig = ((c & 3) << 7) + (c >> 2);
    g_Bwh[t] = __float2half(Ww[orig * DIN + k]);
}

__global__ void build_upair(const float* __restrict__ Uf1,
                            const float* __restrict__ Uf2,
                            const float* __restrict__ Uiuo) {
    int t = blockIdx.x * blockDim.x + threadIdx.x;
    if (t >= NP * 128) return;
    int c = t >> 7;
    int k = t & 127;
    int half = c / 640;
    int r = c - half * 640;
    int w = r >> 7;
    int d = r & 127;
    int sc = half * 128 + k;
    float v;
    if (w == 0)      v = Uf1[d * DIN + sc];
    else if (w == 1) v = Uf2[d * DIN + sc];
    else             v = Uiuo[((w - 2) * DOUT + d) * DIN + sc];
    g_Upair[t] = v;
    g_Uph[t] = __float2half(v);
}

// one warp per output c, shuffle reduction
__global__ void build_pinit(const float* __restrict__ hInit) {
    int warp = (blockIdx.x * blockDim.x + threadIdx.x) >> 5;
    int lane = threadIdx.x & 31;
    if (warp >= NP) return;
    const float* row = g_Upair + (size_t)warp * 128;
    float s = 0.f;
#pragma unroll
    for (int k = 0; k < 4; k++) {
        int kk = lane + k * 32;
        s = fmaf(hInit[kk], row[kk], s);
    }
#pragma unroll
    for (int o = 16; o > 0; o >>= 1) s += __shfl_xor_sync(0xFFFFFFFF, s, o);
    if (lane == 0) g_Pinit[warp] = s;
}

// ---------------- fp16 mma.sync GEMM with fused fp32 A conversion ----------
// A read as fp32 (LDG.128 -> CVT -> STS), B fp16 via cp.async.
// MODE 0: tensor @ Ww -> g_WxH (fp16 out, +bias); K=256. mOff = row-block off.
// MODE 1: prevH(outH fp32) @ Upair -> g_P (fp32 out); K=128.
#define SM_PITCH 80
#define SM_ARR   10240              // 128 rows * 80B
#define SM_BUF   20480              // A, B
#define SM_TOT   40960

template<int MODE>
__global__ __launch_bounds__(256, 2) void mma_gemm(const float* __restrict__ Afp, int mOff) {
    constexpr int K   = (MODE == 0) ? DIN : DOUT;
    constexpr int nCh = K / 32;
    constexpr int ldc = (MODE == 0) ? NWX : NP;

    const __half* __restrict__ B = (MODE == 0) ? g_Bwh : g_Uph;

    extern __shared__ char smem[];
    uint32_t sb = smem_to_u32(smem);
    int tid = threadIdx.x;
    int lane = tid & 31, wid = tid >> 5;
    int wm = wid & 1, wn = wid >> 1;
    int bn = blockIdx.x * 128;
    int bm = (mOff + blockIdx.y) * 128;

    float acc[4][4][4];
#pragma unroll
    for (int mi = 0; mi < 4; mi++)
#pragma unroll
        for (int ni = 0; ni < 4; ni++)
#pragma unroll
            for (int e = 0; e < 4; e++) acc[mi][ni][e] = 0.f;

    // A staging: 1024 float4-chunks per 128x32 tile; 4 per thread.
    // chunk u = i*256+tid: row = i*32 + (tid>>3), c = tid&7 (4 floats at c*4).
    int arow = tid >> 3, ac = tid & 7;
    const float* aPtr = Afp + (size_t)(bm + arow) * K + ac * 4;
    uint32_t aSts = (uint32_t)(arow * SM_PITCH + ac * 8);

    // B cp.async: 512 16B-chunks per tile; 2 per thread.
    int ch0 = tid * 2;
    int rowB0 = ch0 >> 2, cb0 = (ch0 & 3);
    int rowB1 = (ch0 + 1) >> 2, cb1 = ((ch0 + 1) & 3);
    const __half* gB0 = B + (size_t)(bn + rowB0) * K + cb0 * 8;
    const __half* gB1 = B + (size_t)(bn + rowB1) * K + cb1 * 8;
    uint32_t sB0 = (uint32_t)(rowB0 * SM_PITCH + cb0 * 16);
    uint32_t sB1 = (uint32_t)(rowB1 * SM_PITCH + cb1 * 16);

    float4 pa[4];

#define LOAD_A_REGS(t) do {                                                \
    int ko = (t) * 32;                                                     \
    _Pragma("unroll")                                                      \
    for (int i = 0; i < 4; i++)                                            \
        pa[i] = *(const float4*)(aPtr + (size_t)(i * 32) * K + ko);        \
} while (0)

#define STS_A(b) do {                                                      \
    uint32_t bo = sb + (uint32_t)(b) * SM_BUF;                             \
    _Pragma("unroll")                                                      \
    for (int i = 0; i < 4; i++) {                                          \
        union { __half2 h[2]; uint2 u; } cv;                               \
        cv.h[0] = __floats2half2_rn(pa[i].x, pa[i].y);                     \
        cv.h[1] = __floats2half2_rn(pa[i].z, pa[i].w);                     \
        *(uint2*)(smem + (bo - sb) + i * 32 * SM_PITCH + aSts) = cv.u;     \
    }                                                                      \
} while (0)

#define LOAD_B(t, b) do {                                                  \
    uint32_t bo = sb + (uint32_t)(b) * SM_BUF;                             \
    int ko = (t) * 32;                                                     \
    cpa16(bo + SM_ARR + sB0, gB0 + ko);                                    \
    cpa16(bo + SM_ARR + sB1, gB1 + ko);                                    \
    CP_COMMIT();                                                           \
} while (0)

    // ldmatrix lane addressing (verified R8-R14)
    int q = lane >> 3, r = lane & 7;
    uint32_t aLane = (uint32_t)(wm * 64 * SM_PITCH + (r + (q & 1) * 8) * SM_PITCH + (q >> 1) * 16);
    uint32_t bLane = (uint32_t)(wn * 32 * SM_PITCH + ((q >> 1) * 8 + r) * SM_PITCH + (q & 1) * 16);

    LOAD_A_REGS(0);
    LOAD_B(0, 0);
    if (nCh > 1) LOAD_B(1, 1);

    for (int t = 0; t < nCh; t++) {
        STS_A(t & 1);
        if (t + 1 < nCh) LOAD_A_REGS(t + 1);
        if (t == nCh - 1) asm volatile("cp.async.wait_group 0;" ::: "memory");
        else              asm volatile("cp.async.wait_group 1;" ::: "memory");
        __syncthreads();

        uint32_t base = sb + (uint32_t)(t & 1) * SM_BUF;
#pragma unroll
        for (int ks = 0; ks < 2; ks++) {
            uint32_t a[4][4], b[4][2];
#pragma unroll
            for (int mi = 0; mi < 4; mi++)
                ldm_x4(base + aLane + mi * (16 * SM_PITCH) + ks * 32,
                       a[mi][0], a[mi][1], a[mi][2], a[mi][3]);
#pragma unroll
            for (int np = 0; np < 2; np++) {
                uint32_t r0, r1, r2, r3;
                ldm_x4(base + SM_ARR + bLane + np * (16 * SM_PITCH) + ks * 32, r0, r1, r2, r3);
                b[2 * np][0] = r0; b[2 * np][1] = r1;
                b[2 * np + 1][0] = r2; b[2 * np + 1][1] = r3;
            }
#pragma unroll
            for (int mi = 0; mi < 4; mi++)
#pragma unroll
                for (int ni = 0; ni < 4; ni++)
                    mma16816(acc[mi][ni], a[mi], b[ni]);
        }
        __syncthreads();
        if (t + 2 < nCh) LOAD_B(t + 2, t & 1);
    }

    // epilogue
    int g = lane >> 2, tc = lane & 3;
#pragma unroll
    for (int mi = 0; mi < 4; mi++) {
        int row0 = bm + wm * 64 + mi * 16 + g;
#pragma unroll
        for (int ni = 0; ni < 4; ni++) {
            int col = bn + wn * 32 + ni * 8 + tc * 2;
            if (MODE == 0) {
                float b0 = g_biasPerm[col], b1 = g_biasPerm[col + 1];
                __half2 h0 = __floats2half2_rn(acc[mi][ni][0] + b0, acc[mi][ni][1] + b1);
                __half2 h1 = __floats2half2_rn(acc[mi][ni][2] + b0, acc[mi][ni][3] + b1);
                *(__half2*)&g_WxH[(size_t)row0 * ldc + col] = h0;
                *(__half2*)&g_WxH[(size_t)(row0 + 8) * ldc + col] = h1;
            } else {
                float2 v0, v1;
                v0.x = acc[mi][ni][0]; v0.y = acc[mi][ni][1];
                v1.x = acc[mi][ni][2]; v1.y = acc[mi][ni][3];
                *(float2*)&g_P[(size_t)row0 * ldc + col] = v0;
                *(float2*)&g_P[(size_t)(row0 + 8) * ldc + col] = v1;
            }
        }
    }
#undef LOAD_A_REGS
#undef STS_A
#undef LOAD_B
}

// ---------------- LSTM gate epilogue ----------------
__global__ __launch_bounds__(256) void epilogue_kernel(
    int lvl,
    const int* __restrict__ indices,
    const float* __restrict__ cInit,
    float* __restrict__ outH,
    float* __restrict__ outC)
{
    int tid = threadIdx.x;
    int n = blockIdx.x * 2 + (tid >> 7);
    int d = tid & 127;

    int i0 = indices[((size_t)lvl * NN + n) * 2 + 0];
    int i1 = indices[((size_t)lvl * NN + n) * 2 + 1];
    bool L0 = (lvl == 0);

    float p0[5], p1[5];
    if (!L0 && i0 >= 0) {
        const float* rr = g_P + (size_t)i0 * NP;
#pragma unroll
        for (int w = 0; w < 5; w++) p0[w] = rr[w * 128 + d];
    } else {
#pragma unroll
        for (int w = 0; w < 5; w++) p0[w] = g_Pinit[w * 128 + d];
    }
    if (!L0 && i1 >= 0) {
        const float* rr = g_P + (size_t)i1 * NP + 640;
#pragma unroll
        for (int w = 0; w < 5; w++) p1[w] = rr[w * 128 + d];
    } else {
#pragma unroll
        for (int w = 0; w < 5; w++) p1[w] = g_Pinit[640 + w * 128 + d];
    }

    // g_WxH: 4 fp16 per (n,d): f_x, i_x, u_x, o_x
    union { uint2 u; __half h[4]; } wv;
    wv.u = *(const uint2*)&g_WxH[(((size_t)lvl * NN + n) << 9) + (d << 2)];
    float fx = __half2float(wv.h[0]);
    float ix = __half2float(wv.h[1]);
    float ux = __half2float(wv.h[2]);
    float ox = __half2float(wv.h[3]);

    float f1 = sigmoidf_(fx + p0[0] + p1[0]);
    float f2 = sigmoidf_(fx + p0[1] + p1[1]);
    float ig = sigmoidf_(ix + p0[2] + p1[2]);
    float ug = tanhf(ux + p0[3] + p1[3]);
    float og = sigmoidf_(ox + p0[4] + p1[4]);

    const float* prevC = outC + (size_t)(lvl - 1) * NN * DOUT;
    float cc0 = (!L0 && i0 >= 0) ? prevC[(size_t)i0 * DOUT + d] : cInit[d];
    float cc1 = (!L0 && i1 >= 0) ? prevC[(size_t)i1 * DOUT + d] : cInit[d];

    float nc = ig * ug + f1 * cc0 + f2 * cc1;
    float nh = og * tanhf(nc);

    size_t o = ((size_t)lvl * NN + n) * DOUT + d;
    outH[o] = nh;
    outC[o] = nc;
}

extern "C" void kernel_launch(void* const* d_in, const int* in_sizes, int n_in,
                              void* d_out, int out_size) {
    const float* tensor = (const float*)d_in[0];   // [L, N, DIN]
    const int*   indices = (const int*)d_in[1];    // [L, N, 2]
    const float* h_init = (const float*)d_in[2];   // [1, DOUT]
    const float* c_init = (const float*)d_in[3];   // [1, DOUT]
    const float* W_w   = (const float*)d_in[4];    // [4*DOUT, DIN]
    const float* W_b   = (const float*)d_in[5];    // [4*DOUT]
    const float* U_f1  = (const float*)d_in[6];    // [DOUT, 2*DOUT]
    const float* U_f2  = (const float*)d_in[7];
    const float* U_iuo = (const float*)d_in[8];    // [3*DOUT, 2*DOUT]

    float* outH = (float*)d_out;                         // res_h [L,N,DOUT]
    float* outC = outH + (size_t)LL * NN * DOUT;         // res_c [L,N,DOUT]

    cudaFuncSetAttribute(mma_gemm<0>, cudaFuncAttributeMaxDynamicSharedMemorySize, SM_TOT);
    cudaFuncSetAttribute(mma_gemm<1>, cudaFuncAttributeMaxDynamicSharedMemorySize, SM_TOT);

    cudaStream_t s1 = g_res.s1;

    // main stream: weight prep needed by side stream first
    build_bw<<<(NWX * DIN + 255) / 256, 256>>>(W_w, W_b);
    cudaEventRecord(g_res.evStart, 0);

    // side stream: per-level pre-GEMM chunks (A = raw fp32 tensor, fused cvt)
    cudaStreamWaitEvent(s1, g_res.evStart, 0);
    for (int lvl = 0; lvl < LL; lvl++) {
        dim3 g(NWX / 128, 64);
        mma_gemm<0><<<g, 256, SM_TOT, s1>>>(tensor, lvl * 64);
        cudaEventRecord(g_res.ev[lvl], s1);
    }

    // main stream: remaining prep + recurrent chain
    build_upair<<<(NP * 128 + 255) / 256, 256>>>(U_f1, U_f2, U_iuo);
    build_pinit<<<(NP * 32 + 255) / 256, 256>>>(h_init);

    dim3 pg(NP / 128, NN / 128);                         // (10, 64)
    for (int lvl = 0; lvl < LL; lvl++) {
        if (lvl > 0) {
            const float* prevH = outH + (size_t)(lvl - 1) * NN * DOUT;
            mma_gemm<1><<<pg, 256, SM_TOT>>>(prevH, 0);
        }
        cudaStreamWaitEvent(0, g_res.ev[lvl], 0);
        epilogue_kernel<<<NN / 2, 256>>>(lvl, indices, c_init, outH, outC);
    }
}